// round 15
// baseline (speedup 1.0000x reference)
#include <cuda_runtime.h>
#include <cuda_fp16.h>
#include <cstdint>

#define D        128
#define NMAX     100000
#define EMAX     1600000
#define TILE_M   128
#define GT       256     // gemm threads (8 warps)

// ---------------------------------------------------------------------------
// Device scratch
// ---------------------------------------------------------------------------
__device__ __half g_xh[(size_t)NMAX * D];   // fp16 copy of x
__device__ int    g_cnt[NMAX];
__device__ int    g_off[NMAX + 1];
__device__ int    g_bsum[256];
__device__ int    g_barrier;
__device__ int    g_rank[EMAX];             // within-dst rank of each edge
__device__ int2   g_epk[EMAX];              // packed {src, bits(e_attn)} sorted by dst

// ---------------------------------------------------------------------------
// zero counts + spin-barrier counter
// ---------------------------------------------------------------------------
__global__ void zero_cnt_kernel(int n) {
    int i0 = blockIdx.x * blockDim.x + threadIdx.x;
    if (i0 == 0) g_barrier = 0;
    for (int i = i0; i < n; i += gridDim.x * blockDim.x)
        g_cnt[i] = 0;
}

// ---------------------------------------------------------------------------
// x -> fp16 copy (side stream, overlapped with CSR build)
// ---------------------------------------------------------------------------
__global__ void convert_x_kernel(const float* __restrict__ x, int n8) {
    for (int i = blockIdx.x * blockDim.x + threadIdx.x; i < n8;
         i += gridDim.x * blockDim.x) {
        const float* xp = x + (size_t)i * 8;
        float4 a = *reinterpret_cast<const float4*>(xp);
        float4 b = *reinterpret_cast<const float4*>(xp + 4);
        uint4 u;
        __half2 h;
        h = __float22half2_rn(make_float2(a.x, a.y)); u.x = *reinterpret_cast<uint32_t*>(&h);
        h = __float22half2_rn(make_float2(a.z, a.w)); u.y = *reinterpret_cast<uint32_t*>(&h);
        h = __float22half2_rn(make_float2(b.x, b.y)); u.z = *reinterpret_cast<uint32_t*>(&h);
        h = __float22half2_rn(make_float2(b.z, b.w)); u.w = *reinterpret_cast<uint32_t*>(&h);
        *reinterpret_cast<uint4*>(g_xh + (size_t)i * 8) = u;
    }
}

// ---------------------------------------------------------------------------
// CSR build
// ---------------------------------------------------------------------------
__global__ void hist_kernel(const int* __restrict__ dst, int E) {
    int e = blockIdx.x * blockDim.x + threadIdx.x;
    if (e < E) g_rank[e] = atomicAdd(&g_cnt[dst[e]], 1);
}

__global__ void scanoff_kernel(int n) {
    __shared__ int sbm[256];
    __shared__ int sh[256];
    const int tid = threadIdx.x;
    const int chunk = (n + 255) >> 8;
    const int lo = blockIdx.x * chunk;
    int hi = lo + chunk; if (hi > n) hi = n;

    const int sub = (chunk + 255) >> 8;
    int tlo = lo + tid * sub;
    int thi = tlo + sub; if (thi > hi) thi = hi;
    int s = 0;
    for (int i = tlo; i < thi; ++i) s += g_cnt[i];
    sh[tid] = s;
    __syncthreads();
    sbm[tid] = sh[tid];
    __syncthreads();
    for (int d = 128; d; d >>= 1) {
        if (tid < d) sbm[tid] += sbm[tid + d];
        __syncthreads();
    }
    if (tid == 0) {
        g_bsum[blockIdx.x] = sbm[0];
        __threadfence();
        atomicAdd(&g_barrier, 1);
        while (atomicAdd(&g_barrier, 0) < gridDim.x) { }
    }
    __syncthreads();

    int bv = g_bsum[tid];
    sbm[tid] = bv;
    __syncthreads();
    for (int d = 1; d < 256; d <<= 1) {
        int t = (tid >= d) ? sbm[tid - d] : 0;
        __syncthreads();
        sbm[tid] += t;
        __syncthreads();
    }
    if (blockIdx.x == 0 && tid == 0) g_off[n] = sbm[255];
    int block_base = sbm[blockIdx.x] - g_bsum[blockIdx.x];

    int myv = sh[tid];
    __syncthreads();
    for (int d = 1; d < 256; d <<= 1) {
        int t = (tid >= d) ? sh[tid - d] : 0;
        __syncthreads();
        sh[tid] += t;
        __syncthreads();
    }
    int run = block_base + sh[tid] - myv;
    for (int i = tlo; i < thi; ++i) {
        g_off[i] = run;
        run += g_cnt[i];
    }
}

__global__ void fill_kernel(const int* __restrict__ src, const int* __restrict__ dst,
                            const float* __restrict__ ea, int E) {
    int e = blockIdx.x * blockDim.x + threadIdx.x;
    if (e < E) {
        int p = g_off[dst[e]] + g_rank[e];
        g_epk[p] = make_int2(src[e], __float_as_int(ea[e]));
    }
}

// ---------------------------------------------------------------------------
// FUSED gather + HMMA GEMM
//   h rows gathered per-tile directly into the smem h-buffer (no g_h).
//   out = lrelu((x+h)@W1^T + b1) + lrelu((x*h)@W2^T + b2)
// ---------------------------------------------------------------------------
#define SM_W1   0
#define SM_W2   32768
#define SM_TILE 65536          // 2 buffers x (xh 32KB + h 32KB)
#define SM_B1   (SM_TILE + 131072)
#define SM_B2   (SM_B1 + 512)
#define SM_TOT  (SM_B2 + 512)  // 197632 bytes

__device__ __forceinline__ uint32_t swz(int row, int kb) {
    return (uint32_t)(row * 256 + (kb ^ ((row & 7) << 4)));
}

__device__ __forceinline__ uint32_t pack_h2(float a, float b) {
    __half2 h = __float22half2_rn(make_float2(a, b));
    return *reinterpret_cast<uint32_t*>(&h);
}

__device__ __forceinline__ float lrelu(float v) {
    return v >= 0.f ? v : 0.01f * v;
}

__device__ __forceinline__ void ldsm_x4(uint32_t* r, uint32_t addr) {
    asm volatile("ldmatrix.sync.aligned.m8n8.x4.shared.b16 {%0,%1,%2,%3}, [%4];"
                 : "=r"(r[0]), "=r"(r[1]), "=r"(r[2]), "=r"(r[3]) : "r"(addr));
}
__device__ __forceinline__ void mma16816(float* c, const uint32_t* a, const uint32_t* b) {
    asm volatile(
        "mma.sync.aligned.m16n8k16.row.col.f32.f16.f16.f32 "
        "{%0,%1,%2,%3}, {%4,%5,%6,%7}, {%8,%9}, {%0,%1,%2,%3};"
        : "+f"(c[0]), "+f"(c[1]), "+f"(c[2]), "+f"(c[3])
        : "r"(a[0]), "r"(a[1]), "r"(a[2]), "r"(a[3]), "r"(b[0]), "r"(b[1]));
}

__device__ __forceinline__ uint32_t hadd2u(uint32_t a, uint32_t b) {
    __half2 r = __hadd2(*reinterpret_cast<__half2*>(&a), *reinterpret_cast<__half2*>(&b));
    return *reinterpret_cast<uint32_t*>(&r);
}
__device__ __forceinline__ uint32_t hmul2u(uint32_t a, uint32_t b) {
    __half2 r = __hmul2(*reinterpret_cast<__half2*>(&a), *reinterpret_cast<__half2*>(&b));
    return *reinterpret_cast<uint32_t*>(&r);
}

#define CP16(dst, src) \
    asm volatile("cp.async.cg.shared.global [%0], [%1], 16;" :: "r"(dst), "l"(src))
#define CP_COMMIT() asm volatile("cp.async.commit_group;" ::: "memory")
#define CP_WAIT(N)  asm volatile("cp.async.wait_group %0;" :: "n"(N) : "memory")

// Stage raw xh tile via cp.async into buffer buf.
__device__ __forceinline__ void stage_xh(uint32_t sb, int buf, int row0,
                                         int n, int tid) {
    uint32_t base = SM_TILE + (uint32_t)buf * 65536;
    #pragma unroll
    for (int it = 0; it < 8; ++it) {
        int i = tid + it * GT;            // 0..2047 chunk index
        int r = i >> 4;
        int c = i & 15;
        int grow = row0 + r;
        if (grow >= n) grow = n - 1;
        CP16(sb + base + swz(r, c << 4), g_xh + (size_t)grow * D + c * 8);
    }
}

__device__ __forceinline__ void acc_edge4(float* acc, uint4 v, float w) {
    float2 a0 = __half22float2(*reinterpret_cast<__half2*>(&v.x));
    float2 a1 = __half22float2(*reinterpret_cast<__half2*>(&v.y));
    float2 a2 = __half22float2(*reinterpret_cast<__half2*>(&v.z));
    float2 a3 = __half22float2(*reinterpret_cast<__half2*>(&v.w));
    acc[0] = fmaf(w, a0.x, acc[0]); acc[1] = fmaf(w, a0.y, acc[1]);
    acc[2] = fmaf(w, a1.x, acc[2]); acc[3] = fmaf(w, a1.y, acc[3]);
    acc[4] = fmaf(w, a2.x, acc[4]); acc[5] = fmaf(w, a2.y, acc[5]);
    acc[6] = fmaf(w, a3.x, acc[6]); acc[7] = fmaf(w, a3.y, acc[7]);
}

// Gather h rows for a tile directly into smem h buffer.
// 16 half-warps x 8 rows; lane covers one 16B chunk (8 dims).
__device__ __forceinline__ void gather_h(char* smem, int buf, int row0,
                                         int n, int tid) {
    const int hw   = tid >> 4;
    const int lane = tid & 15;
    const uint32_t base = SM_TILE + (uint32_t)buf * 65536 + 32768;
    const uint4* xb = reinterpret_cast<const uint4*>(g_xh);
    #pragma unroll 1
    for (int rr = 0; rr < 8; ++rr) {
        const int r = hw * 8 + rr;
        const int grow = row0 + r;
        float acc[8] = {0.f, 0.f, 0.f, 0.f, 0.f, 0.f, 0.f, 0.f};
        if (grow < n) {
            int j   = g_off[grow];
            int end = g_off[grow + 1];
            #pragma unroll 1
            for (; j + 4 <= end; j += 4) {
                int2 p0 = g_epk[j];
                int2 p1 = g_epk[j + 1];
                int2 p2 = g_epk[j + 2];
                int2 p3 = g_epk[j + 3];
                uint4 v0 = __ldg(xb + (size_t)p0.x * 16 + lane);
                uint4 v1 = __ldg(xb + (size_t)p1.x * 16 + lane);
                uint4 v2 = __ldg(xb + (size_t)p2.x * 16 + lane);
                uint4 v3 = __ldg(xb + (size_t)p3.x * 16 + lane);
                acc_edge4(acc, v0, __int_as_float(p0.y));
                acc_edge4(acc, v1, __int_as_float(p1.y));
                acc_edge4(acc, v2, __int_as_float(p2.y));
                acc_edge4(acc, v3, __int_as_float(p3.y));
            }
            #pragma unroll 1
            for (; j < end; ++j) {
                int2 p0 = g_epk[j];
                uint4 v0 = __ldg(xb + (size_t)p0.x * 16 + lane);
                acc_edge4(acc, v0, __int_as_float(p0.y));
            }
        }
        uint4 o;
        o.x = pack_h2(acc[0], acc[1]);
        o.y = pack_h2(acc[2], acc[3]);
        o.z = pack_h2(acc[4], acc[5]);
        o.w = pack_h2(acc[6], acc[7]);
        *reinterpret_cast<uint4*>(smem + base + swz(r, lane << 4)) = o;
    }
}

__global__ __launch_bounds__(GT, 1)
void gemm_kernel(const float* __restrict__ W1, const float* __restrict__ b1,
                 const float* __restrict__ W2, const float* __restrict__ b2,
                 float* __restrict__ out, int n, int ntiles) {
    extern __shared__ char smem[];
    uint32_t sb = (uint32_t)__cvta_generic_to_shared(smem);
    const int tid  = threadIdx.x;
    const int wid  = tid >> 5;
    const int lane = tid & 31;
    const int mbase = (wid >> 1) * 32;
    const int nbase = (wid & 1) * 64;

    // Stage W1, W2 as fp16 (swizzled), biases as f32
    for (int i = tid; i < D * D / 8; i += GT) {
        int row = i >> 4;
        int k0  = (i & 15) << 3;
        const float* w1p = W1 + row * D + k0;
        const float* w2p = W2 + row * D + k0;
        float4 a0 = *reinterpret_cast<const float4*>(w1p);
        float4 a1 = *reinterpret_cast<const float4*>(w1p + 4);
        float4 c0 = *reinterpret_cast<const float4*>(w2p);
        float4 c1 = *reinterpret_cast<const float4*>(w2p + 4);
        uint4 u1, u2;
        u1.x = pack_h2(a0.x, a0.y); u1.y = pack_h2(a0.z, a0.w);
        u1.z = pack_h2(a1.x, a1.y); u1.w = pack_h2(a1.z, a1.w);
        u2.x = pack_h2(c0.x, c0.y); u2.y = pack_h2(c0.z, c0.w);
        u2.z = pack_h2(c1.x, c1.y); u2.w = pack_h2(c1.z, c1.w);
        uint32_t off = swz(row, k0 * 2);
        *reinterpret_cast<uint4*>(smem + SM_W1 + off) = u1;
        *reinterpret_cast<uint4*>(smem + SM_W2 + off) = u2;
    }
    if (tid < D) {
        *reinterpret_cast<float*>(smem + SM_B1 + tid * 4) = b1[tid];
        *reinterpret_cast<float*>(smem + SM_B2 + tid * 4) = b2[tid];
    }

    // Prologue: stage + gather tile0 into buffer 0
    if (blockIdx.x < ntiles) {
        stage_xh(sb, 0, blockIdx.x * TILE_M, n, tid);
        CP_COMMIT();
        gather_h(smem, 0, blockIdx.x * TILE_M, n, tid);
    } else {
        CP_COMMIT();
    }

    int b = 0;
    for (int tile = blockIdx.x; tile < ntiles; tile += gridDim.x) {
        const int row0 = tile * TILE_M;
        const int nxt  = tile + gridDim.x;

        if (nxt < ntiles) {
            stage_xh(sb, b ^ 1, nxt * TILE_M, n, tid);
            CP_COMMIT();
            CP_WAIT(1);
        } else {
            CP_WAIT(0);
        }
        // gather next tile's h while next xh streams in (cp.async in background)
        if (nxt < ntiles) gather_h(smem, b ^ 1, nxt * TILE_M, n, tid);
        __syncthreads();

        const uint32_t base_xh = SM_TILE + (uint32_t)b * 65536;
        const uint32_t base_h  = base_xh + 32768;

        float c1[2][8][4], c2[2][8][4];
        #pragma unroll
        for (int i = 0; i < 2; ++i)
            #pragma unroll
            for (int j = 0; j < 8; ++j)
                #pragma unroll
                for (int q = 0; q < 4; ++q) { c1[i][j][q] = 0.f; c2[i][j][q] = 0.f; }

        // A-fragment double buffer across k-steps
        uint32_t xf[2][2][4], hf[2][2][4];
        const uint32_t arow = (uint32_t)(lane & 15);
        const uint32_t acol = (uint32_t)((lane >> 4) << 4);
        #pragma unroll
        for (int i = 0; i < 2; ++i) {
            uint32_t off = swz(mbase + i * 16 + arow, acol);
            ldsm_x4(xf[0][i], sb + base_xh + off);
            ldsm_x4(hf[0][i], sb + base_h  + off);
        }

        #pragma unroll
        for (int ks = 0; ks < 8; ++ks) {
            const int cur = ks & 1;
            const int nxtb = cur ^ 1;
            if (ks < 7) {
                const int kb1 = (ks + 1) * 32;
                #pragma unroll
                for (int i = 0; i < 2; ++i) {
                    uint32_t off = swz(mbase + i * 16 + arow, kb1 + acol);
                    ldsm_x4(xf[nxtb][i], sb + base_xh + off);
                    ldsm_x4(hf[nxtb][i], sb + base_h  + off);
                }
            }

            uint32_t aA[2][4], aM[2][4];
            #pragma unroll
            for (int i = 0; i < 2; ++i)
                #pragma unroll
                for (int q = 0; q < 4; ++q) {
                    aA[i][q] = hadd2u(xf[cur][i][q], hf[cur][i][q]);
                    aM[i][q] = hmul2u(xf[cur][i][q], hf[cur][i][q]);
                }

            const int kb0 = ks * 32;
            #pragma unroll
            for (int jp = 0; jp < 4; ++jp) {
                uint32_t boff = swz(nbase + jp * 16 + (lane & 15), kb0 + ((lane >> 4) << 4));
                uint32_t w1q[4], w2q[4];
                ldsm_x4(w1q, sb + SM_W1 + boff);
                ldsm_x4(w2q, sb + SM_W2 + boff);
                uint32_t bW1a[2] = {w1q[0], w1q[2]};
                uint32_t bW1b[2] = {w1q[1], w1q[3]};
                uint32_t bW2a[2] = {w2q[0], w2q[2]};
                uint32_t bW2b[2] = {w2q[1], w2q[3]};
                #pragma unroll
                for (int i = 0; i < 2; ++i) {
                    mma16816(c1[i][2*jp + 0], aA[i], bW1a);
                    mma16816(c1[i][2*jp + 1], aA[i], bW1b);
                    mma16816(c2[i][2*jp + 0], aM[i], bW2a);
                    mma16816(c2[i][2*jp + 1], aM[i], bW2b);
                }
            }
        }

        const int rbase = row0 + mbase + (lane >> 2);
        #pragma unroll
        for (int j = 0; j < 8; ++j) {
            int col = nbase + j * 8 + 2 * (lane & 3);
            float2 bb1 = *reinterpret_cast<const float2*>(smem + SM_B1 + col * 4);
            float2 bb2 = *reinterpret_cast<const float2*>(smem + SM_B2 + col * 4);
            #pragma unroll
            for (int i = 0; i < 2; ++i) {
                int r0 = rbase + i * 16;
                if (r0 < n) {
                    float2 o;
                    o.x = lrelu(c1[i][j][0] + bb1.x) + lrelu(c2[i][j][0] + bb2.x);
                    o.y = lrelu(c1[i][j][1] + bb1.y) + lrelu(c2[i][j][1] + bb2.y);
                    *reinterpret_cast<float2*>(out + (size_t)r0 * D + col) = o;
                }
                int r1 = r0 + 8;
                if (r1 < n) {
                    float2 o;
                    o.x = lrelu(c1[i][j][2] + bb1.x) + lrelu(c2[i][j][2] + bb2.x);
                    o.y = lrelu(c1[i][j][3] + bb1.y) + lrelu(c2[i][j][3] + bb2.y);
                    *reinterpret_cast<float2*>(out + (size_t)r1 * D + col) = o;
                }
            }
        }
        __syncthreads();
        b ^= 1;
    }
}

// ---------------------------------------------------------------------------
// Launch — fork convert_x onto a side stream, overlapped with the CSR chain.
// Inputs: x[N*128] f32, src[E] i32, dst[E] i32, e_attn[E] f32,
//         W1[128*128] f32, b1[128] f32, W2[128*128] f32, b2[128] f32
// ---------------------------------------------------------------------------
extern "C" void kernel_launch(void* const* d_in, const int* in_sizes, int n_in,
                              void* d_out, int out_size) {
    const float* x   = (const float*)d_in[0];
    const int*   src = (const int*)  d_in[1];
    const int*   dst = (const int*)  d_in[2];
    const float* ea  = (const float*)d_in[3];
    const float* W1  = (const float*)d_in[4];
    const float* b1  = (const float*)d_in[5];
    const float* W2  = (const float*)d_in[6];
    const float* b2  = (const float*)d_in[7];
    float*       out = (float*)d_out;

    const int n = in_sizes[0] / D;
    const int E = in_sizes[1];

    cudaStream_t s2;
    cudaEvent_t ef, ec;
    cudaStreamCreateWithFlags(&s2, cudaStreamNonBlocking);
    cudaEventCreateWithFlags(&ef, cudaEventDisableTiming);
    cudaEventCreateWithFlags(&ec, cudaEventDisableTiming);

    // fork: convert x -> fp16 on side stream
    cudaEventRecord(ef, 0);
    cudaStreamWaitEvent(s2, ef, 0);
    convert_x_kernel<<<1024, 256, 0, s2>>>(x, n * D / 8);
    cudaEventRecord(ec, s2);

    // CSR chain on main stream
    zero_cnt_kernel<<<256, 256>>>(n);
    hist_kernel<<<(E + 255) / 256, 256>>>(dst, E);
    scanoff_kernel<<<256, 256>>>(n);
    fill_kernel<<<(E + 255) / 256, 256>>>(src, dst, ea, E);

    // join: fused gather+gemm needs g_xh
    cudaStreamWaitEvent(0, ec, 0);

    cudaFuncSetAttribute(gemm_kernel,
                         cudaFuncAttributeMaxDynamicSharedMemorySize, SM_TOT);
    const int ntiles = (n + TILE_M - 1) / TILE_M;
    gemm_kernel<<<148, GT, SM_TOT>>>(W1, b1, W2, b2, out, n, ntiles);

    cudaEventDestroy(ef);
    cudaEventDestroy(ec);
    cudaStreamDestroy(s2);
}

// round 16
// speedup vs baseline: 1.8658x; 1.8658x over previous
#include <cuda_runtime.h>
#include <cuda_fp16.h>
#include <cstdint>

#define D        128
#define NMAX     100000
#define EMAX     1600000
#define TILE_M   128
#define GT       256     // gemm threads (8 warps)

// ---------------------------------------------------------------------------
// Device scratch
// ---------------------------------------------------------------------------
__device__ __half g_h[(size_t)NMAX * D];    // aggregated neighbor features (fp16)
__device__ __half g_xh[(size_t)NMAX * D];   // fp16 copy of x
__device__ int    g_cnt[NMAX];
__device__ int    g_off[NMAX + 1];
__device__ int    g_bsum[256];
__device__ int    g_barrier;
__device__ int    g_rank[EMAX];             // within-dst rank of each edge
__device__ int2   g_epk[EMAX];              // packed {src, bits(e_attn)} sorted by dst

// ---------------------------------------------------------------------------
// zero counts + spin-barrier counter
// ---------------------------------------------------------------------------
__global__ void zero_cnt_kernel(int n) {
    int i0 = blockIdx.x * blockDim.x + threadIdx.x;
    if (i0 == 0) g_barrier = 0;
    for (int i = i0; i < n; i += gridDim.x * blockDim.x)
        g_cnt[i] = 0;
}

// ---------------------------------------------------------------------------
// x -> fp16 copy (side stream, overlapped with CSR build)
// ---------------------------------------------------------------------------
__global__ void convert_x_kernel(const float* __restrict__ x, int n8) {
    for (int i = blockIdx.x * blockDim.x + threadIdx.x; i < n8;
         i += gridDim.x * blockDim.x) {
        const float* xp = x + (size_t)i * 8;
        float4 a = *reinterpret_cast<const float4*>(xp);
        float4 b = *reinterpret_cast<const float4*>(xp + 4);
        uint4 u;
        __half2 h;
        h = __float22half2_rn(make_float2(a.x, a.y)); u.x = *reinterpret_cast<uint32_t*>(&h);
        h = __float22half2_rn(make_float2(a.z, a.w)); u.y = *reinterpret_cast<uint32_t*>(&h);
        h = __float22half2_rn(make_float2(b.x, b.y)); u.z = *reinterpret_cast<uint32_t*>(&h);
        h = __float22half2_rn(make_float2(b.z, b.w)); u.w = *reinterpret_cast<uint32_t*>(&h);
        *reinterpret_cast<uint4*>(g_xh + (size_t)i * 8) = u;
    }
}

// ---------------------------------------------------------------------------
// CSR build
// ---------------------------------------------------------------------------
__global__ void hist_kernel(const int* __restrict__ dst, int E) {
    int e = blockIdx.x * blockDim.x + threadIdx.x;
    if (e < E) g_rank[e] = atomicAdd(&g_cnt[dst[e]], 1);
}

__global__ void scanoff_kernel(int n) {
    __shared__ int sbm[256];
    __shared__ int sh[256];
    const int tid = threadIdx.x;
    const int chunk = (n + 255) >> 8;
    const int lo = blockIdx.x * chunk;
    int hi = lo + chunk; if (hi > n) hi = n;

    const int sub = (chunk + 255) >> 8;
    int tlo = lo + tid * sub;
    int thi = tlo + sub; if (thi > hi) thi = hi;
    int s = 0;
    for (int i = tlo; i < thi; ++i) s += g_cnt[i];
    sh[tid] = s;
    __syncthreads();
    sbm[tid] = sh[tid];
    __syncthreads();
    for (int d = 128; d; d >>= 1) {
        if (tid < d) sbm[tid] += sbm[tid + d];
        __syncthreads();
    }
    if (tid == 0) {
        g_bsum[blockIdx.x] = sbm[0];
        __threadfence();
        atomicAdd(&g_barrier, 1);
        while (atomicAdd(&g_barrier, 0) < gridDim.x) { }
    }
    __syncthreads();

    int bv = g_bsum[tid];
    sbm[tid] = bv;
    __syncthreads();
    for (int d = 1; d < 256; d <<= 1) {
        int t = (tid >= d) ? sbm[tid - d] : 0;
        __syncthreads();
        sbm[tid] += t;
        __syncthreads();
    }
    if (blockIdx.x == 0 && tid == 0) g_off[n] = sbm[255];
    int block_base = sbm[blockIdx.x] - g_bsum[blockIdx.x];

    int myv = sh[tid];
    __syncthreads();
    for (int d = 1; d < 256; d <<= 1) {
        int t = (tid >= d) ? sh[tid - d] : 0;
        __syncthreads();
        sh[tid] += t;
        __syncthreads();
    }
    int run = block_base + sh[tid] - myv;
    for (int i = tlo; i < thi; ++i) {
        g_off[i] = run;
        run += g_cnt[i];
    }
}

__global__ void fill_kernel(const int* __restrict__ src, const int* __restrict__ dst,
                            const float* __restrict__ ea, int E) {
    int e = blockIdx.x * blockDim.x + threadIdx.x;
    if (e < E) {
        int p = g_off[dst[e]] + g_rank[e];
        g_epk[p] = make_int2(src[e], __float_as_int(ea[e]));
    }
}

// ---------------------------------------------------------------------------
// Gather over node range [w0, w1): half-warp per node, uint4 per lane.
// ---------------------------------------------------------------------------
__device__ __forceinline__ void acc_edge4(float* acc, uint4 v, float w) {
    float2 a0 = __half22float2(*reinterpret_cast<__half2*>(&v.x));
    float2 a1 = __half22float2(*reinterpret_cast<__half2*>(&v.y));
    float2 a2 = __half22float2(*reinterpret_cast<__half2*>(&v.z));
    float2 a3 = __half22float2(*reinterpret_cast<__half2*>(&v.w));
    acc[0] = fmaf(w, a0.x, acc[0]); acc[1] = fmaf(w, a0.y, acc[1]);
    acc[2] = fmaf(w, a1.x, acc[2]); acc[3] = fmaf(w, a1.y, acc[3]);
    acc[4] = fmaf(w, a2.x, acc[4]); acc[5] = fmaf(w, a2.y, acc[5]);
    acc[6] = fmaf(w, a3.x, acc[6]); acc[7] = fmaf(w, a3.y, acc[7]);
}

__global__ void gather_kernel(int w0, int w1) {
    int idx  = blockIdx.x * blockDim.x + threadIdx.x;
    int w    = w0 + (idx >> 4);
    if (w >= w1) return;
    int lane = idx & 15;
    int j   = g_off[w];
    int end = g_off[w + 1];
    const uint4* xb = reinterpret_cast<const uint4*>(g_xh);
    const int2* ep = g_epk;
    float acc[8] = {0.f, 0.f, 0.f, 0.f, 0.f, 0.f, 0.f, 0.f};

    #pragma unroll 1
    for (; j + 4 <= end; j += 4) {
        int2 p0 = ep[j];
        int2 p1 = ep[j + 1];
        int2 p2 = ep[j + 2];
        int2 p3 = ep[j + 3];
        uint4 v0 = __ldg(xb + (size_t)p0.x * 16 + lane);
        uint4 v1 = __ldg(xb + (size_t)p1.x * 16 + lane);
        uint4 v2 = __ldg(xb + (size_t)p2.x * 16 + lane);
        uint4 v3 = __ldg(xb + (size_t)p3.x * 16 + lane);
        acc_edge4(acc, v0, __int_as_float(p0.y));
        acc_edge4(acc, v1, __int_as_float(p1.y));
        acc_edge4(acc, v2, __int_as_float(p2.y));
        acc_edge4(acc, v3, __int_as_float(p3.y));
    }
    #pragma unroll 1
    for (; j < end; ++j) {
        int2 p0 = ep[j];
        uint4 v0 = __ldg(xb + (size_t)p0.x * 16 + lane);
        acc_edge4(acc, v0, __int_as_float(p0.y));
    }

    uint4 o;
    o.x = __float_as_int(0.f);  // placeholder overwritten below (keeps regalloc tight)
    __half2 h;
    h = __float22half2_rn(make_float2(acc[0], acc[1])); o.x = *reinterpret_cast<uint32_t*>(&h);
    h = __float22half2_rn(make_float2(acc[2], acc[3])); o.y = *reinterpret_cast<uint32_t*>(&h);
    h = __float22half2_rn(make_float2(acc[4], acc[5])); o.z = *reinterpret_cast<uint32_t*>(&h);
    h = __float22half2_rn(make_float2(acc[6], acc[7])); o.w = *reinterpret_cast<uint32_t*>(&h);
    reinterpret_cast<uint4*>(g_h)[(size_t)w * 16 + lane] = o;
}

// ---------------------------------------------------------------------------
// HMMA GEMM over tile range [t0, t1): R11 internals, 8 warps, warp tile 32x64.
// cp.async double-buffered raw xh/h tiles; bi-interaction on ldmatrix frags.
// ---------------------------------------------------------------------------
#define SM_W1   0
#define SM_W2   32768
#define SM_TILE 65536          // 2 buffers x (xh 32KB + h 32KB)
#define SM_B1   (SM_TILE + 131072)
#define SM_B2   (SM_B1 + 512)
#define SM_TOT  (SM_B2 + 512)  // 197632 bytes

__device__ __forceinline__ uint32_t swz(int row, int kb) {
    return (uint32_t)(row * 256 + (kb ^ ((row & 7) << 4)));
}

__device__ __forceinline__ uint32_t pack_h2(float a, float b) {
    __half2 h = __float22half2_rn(make_float2(a, b));
    return *reinterpret_cast<uint32_t*>(&h);
}

__device__ __forceinline__ float lrelu(float v) {
    return v >= 0.f ? v : 0.01f * v;
}

__device__ __forceinline__ void ldsm_x4(uint32_t* r, uint32_t addr) {
    asm volatile("ldmatrix.sync.aligned.m8n8.x4.shared.b16 {%0,%1,%2,%3}, [%4];"
                 : "=r"(r[0]), "=r"(r[1]), "=r"(r[2]), "=r"(r[3]) : "r"(addr));
}
__device__ __forceinline__ void ldsm_x2(uint32_t* r, uint32_t addr) {
    asm volatile("ldmatrix.sync.aligned.m8n8.x2.shared.b16 {%0,%1}, [%2];"
                 : "=r"(r[0]), "=r"(r[1]) : "r"(addr));
}
__device__ __forceinline__ void mma16816(float* c, const uint32_t* a, const uint32_t* b) {
    asm volatile(
        "mma.sync.aligned.m16n8k16.row.col.f32.f16.f16.f32 "
        "{%0,%1,%2,%3}, {%4,%5,%6,%7}, {%8,%9}, {%0,%1,%2,%3};"
        : "+f"(c[0]), "+f"(c[1]), "+f"(c[2]), "+f"(c[3])
        : "r"(a[0]), "r"(a[1]), "r"(a[2]), "r"(a[3]), "r"(b[0]), "r"(b[1]));
}

__device__ __forceinline__ uint32_t hadd2u(uint32_t a, uint32_t b) {
    __half2 r = __hadd2(*reinterpret_cast<__half2*>(&a), *reinterpret_cast<__half2*>(&b));
    return *reinterpret_cast<uint32_t*>(&r);
}
__device__ __forceinline__ uint32_t hmul2u(uint32_t a, uint32_t b) {
    __half2 r = __hmul2(*reinterpret_cast<__half2*>(&a), *reinterpret_cast<__half2*>(&b));
    return *reinterpret_cast<uint32_t*>(&r);
}

#define CP16(dst, src) \
    asm volatile("cp.async.cg.shared.global [%0], [%1], 16;" :: "r"(dst), "l"(src))
#define CP_COMMIT() asm volatile("cp.async.commit_group;" ::: "memory")
#define CP_WAIT(N)  asm volatile("cp.async.wait_group %0;" :: "n"(N) : "memory")

__device__ __forceinline__ void stage_tile(uint32_t sb, int buf, int row0,
                                           int n, int tid) {
    uint32_t base_xh = SM_TILE + (uint32_t)buf * 65536;
    uint32_t base_h  = base_xh + 32768;
    #pragma unroll
    for (int it = 0; it < 8; ++it) {
        int i = tid + it * GT;
        int r = i >> 4;
        int c = i & 15;
        int grow = row0 + r;
        if (grow >= n) grow = n - 1;
        uint32_t off = swz(r, c << 4);
        const __half* xs = g_xh + (size_t)grow * D + c * 8;
        const __half* hs = g_h  + (size_t)grow * D + c * 8;
        CP16(sb + base_xh + off, xs);
        CP16(sb + base_h  + off, hs);
    }
}

__global__ __launch_bounds__(GT, 1)
void gemm_kernel(const float* __restrict__ W1, const float* __restrict__ b1,
                 const float* __restrict__ W2, const float* __restrict__ b2,
                 float* __restrict__ out, int n, int t0, int t1) {
    extern __shared__ char smem[];
    uint32_t sb = (uint32_t)__cvta_generic_to_shared(smem);
    const int tid  = threadIdx.x;
    const int wid  = tid >> 5;
    const int lane = tid & 31;
    const int mbase = (wid >> 1) * 32;
    const int nbase = (wid & 1) * 64;

    for (int i = tid; i < D * D / 8; i += GT) {
        int row = i >> 4;
        int k0  = (i & 15) << 3;
        const float* w1p = W1 + row * D + k0;
        const float* w2p = W2 + row * D + k0;
        float4 a0 = *reinterpret_cast<const float4*>(w1p);
        float4 a1 = *reinterpret_cast<const float4*>(w1p + 4);
        float4 c0 = *reinterpret_cast<const float4*>(w2p);
        float4 c1 = *reinterpret_cast<const float4*>(w2p + 4);
        uint4 u1, u2;
        u1.x = pack_h2(a0.x, a0.y); u1.y = pack_h2(a0.z, a0.w);
        u1.z = pack_h2(a1.x, a1.y); u1.w = pack_h2(a1.z, a1.w);
        u2.x = pack_h2(c0.x, c0.y); u2.y = pack_h2(c0.z, c0.w);
        u2.z = pack_h2(c1.x, c1.y); u2.w = pack_h2(c1.z, c1.w);
        uint32_t off = swz(row, k0 * 2);
        *reinterpret_cast<uint4*>(smem + SM_W1 + off) = u1;
        *reinterpret_cast<uint4*>(smem + SM_W2 + off) = u2;
    }
    if (tid < D) {
        *reinterpret_cast<float*>(smem + SM_B1 + tid * 4) = b1[tid];
        *reinterpret_cast<float*>(smem + SM_B2 + tid * 4) = b2[tid];
    }

    if (t0 + blockIdx.x < t1) {
        stage_tile(sb, 0, (t0 + blockIdx.x) * TILE_M, n, tid);
    }
    CP_COMMIT();

    int b = 0;
    for (int tile = t0 + blockIdx.x; tile < t1; tile += gridDim.x) {
        const int row0 = tile * TILE_M;
        const int nxt  = tile + gridDim.x;

        if (nxt < t1) {
            stage_tile(sb, b ^ 1, nxt * TILE_M, n, tid);
            CP_COMMIT();
            CP_WAIT(1);
        } else {
            CP_WAIT(0);
        }
        __syncthreads();

        const uint32_t base_xh = SM_TILE + (uint32_t)b * 65536;
        const uint32_t base_h  = base_xh + 32768;

        float c1[2][8][4], c2[2][8][4];
        #pragma unroll
        for (int i = 0; i < 2; ++i)
            #pragma unroll
            for (int j = 0; j < 8; ++j)
                #pragma unroll
                for (int q = 0; q < 4; ++q) { c1[i][j][q] = 0.f; c2[i][j][q] = 0.f; }

        for (int ks = 0; ks < 8; ++ks) {
            const int kb0 = ks * 32;
            uint32_t aA[2][4], aM[2][4];
            #pragma unroll
            for (int i = 0; i < 2; ++i) {
                uint32_t off = swz(mbase + i * 16 + (lane & 15), kb0 + ((lane >> 4) << 4));
                uint32_t xf[4], hf[4];
                ldsm_x4(xf, sb + base_xh + off);
                ldsm_x4(hf, sb + base_h  + off);
                #pragma unroll
                for (int q = 0; q < 4; ++q) {
                    aA[i][q] = hadd2u(xf[q], hf[q]);
                    aM[i][q] = hmul2u(xf[q], hf[q]);
                }
            }
            #pragma unroll
            for (int j = 0; j < 8; ++j) {
                uint32_t boff = swz(nbase + j * 8 + (lane & 7), kb0 + (((lane >> 3) & 1) << 4));
                uint32_t bW1[2], bW2[2];
                ldsm_x2(bW1, sb + SM_W1 + boff);
                ldsm_x2(bW2, sb + SM_W2 + boff);
                #pragma unroll
                for (int i = 0; i < 2; ++i) {
                    mma16816(c1[i][j], aA[i], bW1);
                    mma16816(c2[i][j], aM[i], bW2);
                }
            }
        }

        const int rbase = row0 + mbase + (lane >> 2);
        #pragma unroll
        for (int j = 0; j < 8; ++j) {
            int col = nbase + j * 8 + 2 * (lane & 3);
            float2 bb1 = *reinterpret_cast<const float2*>(smem + SM_B1 + col * 4);
            float2 bb2 = *reinterpret_cast<const float2*>(smem + SM_B2 + col * 4);
            #pragma unroll
            for (int i = 0; i < 2; ++i) {
                int r0 = rbase + i * 16;
                if (r0 < n) {
                    float2 o;
                    o.x = lrelu(c1[i][j][0] + bb1.x) + lrelu(c2[i][j][0] + bb2.x);
                    o.y = lrelu(c1[i][j][1] + bb1.y) + lrelu(c2[i][j][1] + bb2.y);
                    *reinterpret_cast<float2*>(out + (size_t)r0 * D + col) = o;
                }
                int r1 = r0 + 8;
                if (r1 < n) {
                    float2 o;
                    o.x = lrelu(c1[i][j][2] + bb1.x) + lrelu(c2[i][j][2] + bb2.x);
                    o.y = lrelu(c1[i][j][3] + bb1.y) + lrelu(c2[i][j][3] + bb2.y);
                    *reinterpret_cast<float2*>(out + (size_t)r1 * D + col) = o;
                }
            }
        }
        __syncthreads();
        b ^= 1;
    }
}

// ---------------------------------------------------------------------------
// Launch — convert_x forked; gather/gemm pipelined in two halves across
// two streams so gather(hi) overlaps gemm(lo).
// Inputs: x[N*128] f32, src[E] i32, dst[E] i32, e_attn[E] f32,
//         W1[128*128] f32, b1[128] f32, W2[128*128] f32, b2[128] f32
// ---------------------------------------------------------------------------
extern "C" void kernel_launch(void* const* d_in, const int* in_sizes, int n_in,
                              void* d_out, int out_size) {
    const float* x   = (const float*)d_in[0];
    const int*   src = (const int*)  d_in[1];
    const int*   dst = (const int*)  d_in[2];
    const float* ea  = (const float*)d_in[3];
    const float* W1  = (const float*)d_in[4];
    const float* b1  = (const float*)d_in[5];
    const float* W2  = (const float*)d_in[6];
    const float* b2  = (const float*)d_in[7];
    float*       out = (float*)d_out;

    const int n = in_sizes[0] / D;
    const int E = in_sizes[1];
    const int ntiles = (n + TILE_M - 1) / TILE_M;
    const int tLo = ntiles / 2;
    const int nLo = tLo * TILE_M;        // rows in low half (tile-aligned)

    cudaFuncSetAttribute(gemm_kernel,
                         cudaFuncAttributeMaxDynamicSharedMemorySize, SM_TOT);

    cudaStream_t s2, s3;
    cudaEvent_t ef, ec, eLo, eHi, eF;
    cudaStreamCreateWithFlags(&s2, cudaStreamNonBlocking);
    cudaStreamCreateWithFlags(&s3, cudaStreamNonBlocking);
    cudaEventCreateWithFlags(&ef,  cudaEventDisableTiming);
    cudaEventCreateWithFlags(&ec,  cudaEventDisableTiming);
    cudaEventCreateWithFlags(&eLo, cudaEventDisableTiming);
    cudaEventCreateWithFlags(&eHi, cudaEventDisableTiming);
    cudaEventCreateWithFlags(&eF,  cudaEventDisableTiming);

    // fork: convert x -> fp16 on side stream
    cudaEventRecord(ef, 0);
    cudaStreamWaitEvent(s2, ef, 0);
    convert_x_kernel<<<1024, 256, 0, s2>>>(x, n * D / 8);
    cudaEventRecord(ec, s2);

    // CSR chain on main stream
    zero_cnt_kernel<<<256, 256>>>(n);
    hist_kernel<<<(E + 255) / 256, 256>>>(dst, E);
    scanoff_kernel<<<256, 256>>>(n);
    fill_kernel<<<(E + 255) / 256, 256>>>(src, dst, ea, E);

    // join convert before gather
    cudaStreamWaitEvent(0, ec, 0);

    // gather low half, signal, gather high half, signal
    gather_kernel<<<(nLo + 15) / 16, 256>>>(0, nLo);
    cudaEventRecord(eLo, 0);
    gather_kernel<<<(n - nLo + 15) / 16, 256>>>(nLo, n);
    cudaEventRecord(eHi, 0);

    // side stream: gemm(lo) overlaps gather(hi); then gemm(hi)
    cudaStreamWaitEvent(s3, eLo, 0);
    gemm_kernel<<<148, GT, SM_TOT, s3>>>(W1, b1, W2, b2, out, n, 0, tLo);
    cudaStreamWaitEvent(s3, eHi, 0);
    gemm_kernel<<<148, GT, SM_TOT, s3>>>(W1, b1, W2, b2, out, n, tLo, ntiles);
    cudaEventRecord(eF, s3);

    // join back to main stream
    cudaStreamWaitEvent(0, eF, 0);

    cudaEventDestroy(ef);
    cudaEventDestroy(ec);
    cudaEventDestroy(eLo);
    cudaEventDestroy(eHi);
    cudaEventDestroy(eF);
    cudaStreamDestroy(s2);
    cudaStreamDestroy(s3);
}

// round 17
// speedup vs baseline: 1.9141x; 1.0259x over previous
#include <cuda_runtime.h>
#include <cuda_fp16.h>
#include <cstdint>

#define D        128
#define NMAX     100000
#define EMAX     1600000
#define TILE_M   128
#define GT       256     // gemm threads (8 warps)

// ---------------------------------------------------------------------------
// Device scratch (static zero-init covers first call; fill re-zeroes g_cnt
// and g_barrier at its end for every subsequent graph replay)
// ---------------------------------------------------------------------------
__device__ __half g_h[(size_t)NMAX * D];    // aggregated neighbor features (fp16)
__device__ __half g_xh[(size_t)NMAX * D];   // fp16 copy of x
__device__ int    g_cnt[NMAX];
__device__ int    g_off[NMAX + 1];
__device__ int    g_bsum[256];
__device__ int    g_barrier;
__device__ int    g_rank[EMAX];             // within-dst rank of each edge
__device__ int2   g_epk[EMAX];              // packed {src, bits(e_attn)} sorted by dst

// ---------------------------------------------------------------------------
// x -> fp16 copy (side stream, overlapped with CSR build)
// ---------------------------------------------------------------------------
__global__ void convert_x_kernel(const float* __restrict__ x, int n8) {
    for (int i = blockIdx.x * blockDim.x + threadIdx.x; i < n8;
         i += gridDim.x * blockDim.x) {
        const float* xp = x + (size_t)i * 8;
        float4 a = *reinterpret_cast<const float4*>(xp);
        float4 b = *reinterpret_cast<const float4*>(xp + 4);
        uint4 u;
        __half2 h;
        h = __float22half2_rn(make_float2(a.x, a.y)); u.x = *reinterpret_cast<uint32_t*>(&h);
        h = __float22half2_rn(make_float2(a.z, a.w)); u.y = *reinterpret_cast<uint32_t*>(&h);
        h = __float22half2_rn(make_float2(b.x, b.y)); u.z = *reinterpret_cast<uint32_t*>(&h);
        h = __float22half2_rn(make_float2(b.z, b.w)); u.w = *reinterpret_cast<uint32_t*>(&h);
        *reinterpret_cast<uint4*>(g_xh + (size_t)i * 8) = u;
    }
}

// ---------------------------------------------------------------------------
// CSR build
// ---------------------------------------------------------------------------
__global__ void hist_kernel(const int* __restrict__ dst, int E) {
    int e = blockIdx.x * blockDim.x + threadIdx.x;
    if (e < E) g_rank[e] = atomicAdd(&g_cnt[dst[e]], 1);
}

// merged bsum + offwrite with global spin barrier (256 blocks, all resident)
__global__ void scanoff_kernel(int n) {
    __shared__ int sbm[256];
    __shared__ int sh[256];
    const int tid = threadIdx.x;
    const int chunk = (n + 255) >> 8;
    const int lo = blockIdx.x * chunk;
    int hi = lo + chunk; if (hi > n) hi = n;

    const int sub = (chunk + 255) >> 8;
    int tlo = lo + tid * sub;
    int thi = tlo + sub; if (thi > hi) thi = hi;
    int s = 0;
    for (int i = tlo; i < thi; ++i) s += g_cnt[i];
    sh[tid] = s;
    __syncthreads();
    sbm[tid] = sh[tid];
    __syncthreads();
    for (int d = 128; d; d >>= 1) {
        if (tid < d) sbm[tid] += sbm[tid + d];
        __syncthreads();
    }
    if (tid == 0) {
        g_bsum[blockIdx.x] = sbm[0];
        __threadfence();
        atomicAdd(&g_barrier, 1);
        while (atomicAdd(&g_barrier, 0) < gridDim.x) { }
    }
    __syncthreads();

    int bv = g_bsum[tid];
    sbm[tid] = bv;
    __syncthreads();
    for (int d = 1; d < 256; d <<= 1) {
        int t = (tid >= d) ? sbm[tid - d] : 0;
        __syncthreads();
        sbm[tid] += t;
        __syncthreads();
    }
    if (blockIdx.x == 0 && tid == 0) g_off[n] = sbm[255];
    int block_base = sbm[blockIdx.x] - g_bsum[blockIdx.x];

    int myv = sh[tid];
    __syncthreads();
    for (int d = 1; d < 256; d <<= 1) {
        int t = (tid >= d) ? sh[tid - d] : 0;
        __syncthreads();
        sh[tid] += t;
        __syncthreads();
    }
    int run = block_base + sh[tid] - myv;
    for (int i = tlo; i < thi; ++i) {
        g_off[i] = run;
        run += g_cnt[i];
    }
}

// fill (atomic-free) + re-zero g_cnt / g_barrier for the next graph replay
__global__ void fill_kernel(const int* __restrict__ src, const int* __restrict__ dst,
                            const float* __restrict__ ea, int E, int n) {
    int e = blockIdx.x * blockDim.x + threadIdx.x;
    if (e < E) {
        int p = g_off[dst[e]] + g_rank[e];
        g_epk[p] = make_int2(src[e], __float_as_int(ea[e]));
    }
    // g_cnt is dead after scanoff; reset it here for the next replay.
    if (e < n) g_cnt[e] = 0;
    if (e == 0) g_barrier = 0;
}

// ---------------------------------------------------------------------------
// Gather: half-warp (16 lanes) per node; uint4 per lane covers 256B row.
// fp32 accumulation, unroll-8 for deeper MLP, fp16 result store.
// ---------------------------------------------------------------------------
__device__ __forceinline__ void acc_edge4(float* acc, uint4 v, float w) {
    float2 a0 = __half22float2(*reinterpret_cast<__half2*>(&v.x));
    float2 a1 = __half22float2(*reinterpret_cast<__half2*>(&v.y));
    float2 a2 = __half22float2(*reinterpret_cast<__half2*>(&v.z));
    float2 a3 = __half22float2(*reinterpret_cast<__half2*>(&v.w));
    acc[0] = fmaf(w, a0.x, acc[0]); acc[1] = fmaf(w, a0.y, acc[1]);
    acc[2] = fmaf(w, a1.x, acc[2]); acc[3] = fmaf(w, a1.y, acc[3]);
    acc[4] = fmaf(w, a2.x, acc[4]); acc[5] = fmaf(w, a2.y, acc[5]);
    acc[6] = fmaf(w, a3.x, acc[6]); acc[7] = fmaf(w, a3.y, acc[7]);
}

__global__ void gather_kernel(int n) {
    int idx  = blockIdx.x * blockDim.x + threadIdx.x;
    int w    = idx >> 4;
    if (w >= n) return;
    int lane = idx & 15;
    int j   = g_off[w];
    int end = g_off[w + 1];
    const uint4* xb = reinterpret_cast<const uint4*>(g_xh);
    const int2* ep = g_epk;
    float acc[8] = {0.f, 0.f, 0.f, 0.f, 0.f, 0.f, 0.f, 0.f};

    #pragma unroll 1
    for (; j + 8 <= end; j += 8) {
        int2 p[8];
        #pragma unroll
        for (int t = 0; t < 8; ++t) p[t] = ep[j + t];
        uint4 v[8];
        #pragma unroll
        for (int t = 0; t < 8; ++t)
            v[t] = __ldg(xb + (size_t)p[t].x * 16 + lane);
        #pragma unroll
        for (int t = 0; t < 8; ++t)
            acc_edge4(acc, v[t], __int_as_float(p[t].y));
    }
    #pragma unroll 1
    for (; j + 2 <= end; j += 2) {
        int2 p0 = ep[j];
        int2 p1 = ep[j + 1];
        uint4 v0 = __ldg(xb + (size_t)p0.x * 16 + lane);
        uint4 v1 = __ldg(xb + (size_t)p1.x * 16 + lane);
        acc_edge4(acc, v0, __int_as_float(p0.y));
        acc_edge4(acc, v1, __int_as_float(p1.y));
    }
    if (j < end) {
        int2 p0 = ep[j];
        uint4 v0 = __ldg(xb + (size_t)p0.x * 16 + lane);
        acc_edge4(acc, v0, __int_as_float(p0.y));
    }

    uint4 o;
    __half2 h;
    h = __float22half2_rn(make_float2(acc[0], acc[1])); o.x = *reinterpret_cast<uint32_t*>(&h);
    h = __float22half2_rn(make_float2(acc[2], acc[3])); o.y = *reinterpret_cast<uint32_t*>(&h);
    h = __float22half2_rn(make_float2(acc[4], acc[5])); o.z = *reinterpret_cast<uint32_t*>(&h);
    h = __float22half2_rn(make_float2(acc[6], acc[7])); o.w = *reinterpret_cast<uint32_t*>(&h);
    reinterpret_cast<uint4*>(g_h)[(size_t)w * 16 + lane] = o;
}

// ---------------------------------------------------------------------------
// HMMA GEMM (R11 verbatim): out = lrelu((x+h)@W1^T+b1) + lrelu((x*h)@W2^T+b2)
// 8 warps, warp tile 32x64; cp.async double-buffered raw xh/h tiles;
// bi-interaction computed on ldmatrix fragments.
// ---------------------------------------------------------------------------
#define SM_W1   0
#define SM_W2   32768
#define SM_TILE 65536          // 2 buffers x (xh 32KB + h 32KB)
#define SM_B1   (SM_TILE + 131072)
#define SM_B2   (SM_B1 + 512)
#define SM_TOT  (SM_B2 + 512)  // 197632 bytes

__device__ __forceinline__ uint32_t swz(int row, int kb) {
    return (uint32_t)(row * 256 + (kb ^ ((row & 7) << 4)));
}

__device__ __forceinline__ uint32_t pack_h2(float a, float b) {
    __half2 h = __float22half2_rn(make_float2(a, b));
    return *reinterpret_cast<uint32_t*>(&h);
}

__device__ __forceinline__ float lrelu(float v) {
    return v >= 0.f ? v : 0.01f * v;
}

__device__ __forceinline__ void ldsm_x4(uint32_t* r, uint32_t addr) {
    asm volatile("ldmatrix.sync.aligned.m8n8.x4.shared.b16 {%0,%1,%2,%3}, [%4];"
                 : "=r"(r[0]), "=r"(r[1]), "=r"(r[2]), "=r"(r[3]) : "r"(addr));
}
__device__ __forceinline__ void ldsm_x2(uint32_t* r, uint32_t addr) {
    asm volatile("ldmatrix.sync.aligned.m8n8.x2.shared.b16 {%0,%1}, [%2];"
                 : "=r"(r[0]), "=r"(r[1]) : "r"(addr));
}
__device__ __forceinline__ void mma16816(float* c, const uint32_t* a, const uint32_t* b) {
    asm volatile(
        "mma.sync.aligned.m16n8k16.row.col.f32.f16.f16.f32 "
        "{%0,%1,%2,%3}, {%4,%5,%6,%7}, {%8,%9}, {%0,%1,%2,%3};"
        : "+f"(c[0]), "+f"(c[1]), "+f"(c[2]), "+f"(c[3])
        : "r"(a[0]), "r"(a[1]), "r"(a[2]), "r"(a[3]), "r"(b[0]), "r"(b[1]));
}

__device__ __forceinline__ uint32_t hadd2u(uint32_t a, uint32_t b) {
    __half2 r = __hadd2(*reinterpret_cast<__half2*>(&a), *reinterpret_cast<__half2*>(&b));
    return *reinterpret_cast<uint32_t*>(&r);
}
__device__ __forceinline__ uint32_t hmul2u(uint32_t a, uint32_t b) {
    __half2 r = __hmul2(*reinterpret_cast<__half2*>(&a), *reinterpret_cast<__half2*>(&b));
    return *reinterpret_cast<uint32_t*>(&r);
}

#define CP16(dst, src) \
    asm volatile("cp.async.cg.shared.global [%0], [%1], 16;" :: "r"(dst), "l"(src))
#define CP_COMMIT() asm volatile("cp.async.commit_group;" ::: "memory")
#define CP_WAIT(N)  asm volatile("cp.async.wait_group %0;" :: "n"(N) : "memory")

__device__ __forceinline__ void stage_tile(uint32_t sb, int buf, int row0,
                                           int n, int tid) {
    uint32_t base_xh = SM_TILE + (uint32_t)buf * 65536;
    uint32_t base_h  = base_xh + 32768;
    #pragma unroll
    for (int it = 0; it < 8; ++it) {
        int i = tid + it * GT;
        int r = i >> 4;
        int c = i & 15;
        int grow = row0 + r;
        if (grow >= n) grow = n - 1;
        uint32_t off = swz(r, c << 4);
        const __half* xs = g_xh + (size_t)grow * D + c * 8;
        const __half* hs = g_h  + (size_t)grow * D + c * 8;
        CP16(sb + base_xh + off, xs);
        CP16(sb + base_h  + off, hs);
    }
}

__global__ __launch_bounds__(GT, 1)
void gemm_kernel(const float* __restrict__ W1, const float* __restrict__ b1,
                 const float* __restrict__ W2, const float* __restrict__ b2,
                 float* __restrict__ out, int n, int ntiles) {
    extern __shared__ char smem[];
    uint32_t sb = (uint32_t)__cvta_generic_to_shared(smem);
    const int tid  = threadIdx.x;
    const int wid  = tid >> 5;
    const int lane = tid & 31;
    const int mbase = (wid >> 1) * 32;
    const int nbase = (wid & 1) * 64;

    for (int i = tid; i < D * D / 8; i += GT) {
        int row = i >> 4;
        int k0  = (i & 15) << 3;
        const float* w1p = W1 + row * D + k0;
        const float* w2p = W2 + row * D + k0;
        float4 a0 = *reinterpret_cast<const float4*>(w1p);
        float4 a1 = *reinterpret_cast<const float4*>(w1p + 4);
        float4 c0 = *reinterpret_cast<const float4*>(w2p);
        float4 c1 = *reinterpret_cast<const float4*>(w2p + 4);
        uint4 u1, u2;
        u1.x = pack_h2(a0.x, a0.y); u1.y = pack_h2(a0.z, a0.w);
        u1.z = pack_h2(a1.x, a1.y); u1.w = pack_h2(a1.z, a1.w);
        u2.x = pack_h2(c0.x, c0.y); u2.y = pack_h2(c0.z, c0.w);
        u2.z = pack_h2(c1.x, c1.y); u2.w = pack_h2(c1.z, c1.w);
        uint32_t off = swz(row, k0 * 2);
        *reinterpret_cast<uint4*>(smem + SM_W1 + off) = u1;
        *reinterpret_cast<uint4*>(smem + SM_W2 + off) = u2;
    }
    if (tid < D) {
        *reinterpret_cast<float*>(smem + SM_B1 + tid * 4) = b1[tid];
        *reinterpret_cast<float*>(smem + SM_B2 + tid * 4) = b2[tid];
    }

    if (blockIdx.x < ntiles) {
        stage_tile(sb, 0, blockIdx.x * TILE_M, n, tid);
    }
    CP_COMMIT();

    int b = 0;
    for (int tile = blockIdx.x; tile < ntiles; tile += gridDim.x) {
        const int row0 = tile * TILE_M;
        const int nxt  = tile + gridDim.x;

        if (nxt < ntiles) {
            stage_tile(sb, b ^ 1, nxt * TILE_M, n, tid);
            CP_COMMIT();
            CP_WAIT(1);
        } else {
            CP_WAIT(0);
        }
        __syncthreads();

        const uint32_t base_xh = SM_TILE + (uint32_t)b * 65536;
        const uint32_t base_h  = base_xh + 32768;

        float c1[2][8][4], c2[2][8][4];
        #pragma unroll
        for (int i = 0; i < 2; ++i)
            #pragma unroll
            for (int j = 0; j < 8; ++j)
                #pragma unroll
                for (int q = 0; q < 4; ++q) { c1[i][j][q] = 0.f; c2[i][j][q] = 0.f; }

        for (int ks = 0; ks < 8; ++ks) {
            const int kb0 = ks * 32;
            uint32_t aA[2][4], aM[2][4];
            #pragma unroll
            for (int i = 0; i < 2; ++i) {
                uint32_t off = swz(mbase + i * 16 + (lane & 15), kb0 + ((lane >> 4) << 4));
                uint32_t xf[4], hf[4];
                ldsm_x4(xf, sb + base_xh + off);
                ldsm_x4(hf, sb + base_h  + off);
                #pragma unroll
                for (int q = 0; q < 4; ++q) {
                    aA[i][q] = hadd2u(xf[q], hf[q]);
                    aM[i][q] = hmul2u(xf[q], hf[q]);
                }
            }
            #pragma unroll
            for (int j = 0; j < 8; ++j) {
                uint32_t boff = swz(nbase + j * 8 + (lane & 7), kb0 + (((lane >> 3) & 1) << 4));
                uint32_t bW1[2], bW2[2];
                ldsm_x2(bW1, sb + SM_W1 + boff);
                ldsm_x2(bW2, sb + SM_W2 + boff);
                #pragma unroll
                for (int i = 0; i < 2; ++i) {
                    mma16816(c1[i][j], aA[i], bW1);
                    mma16816(c2[i][j], aM[i], bW2);
                }
            }
        }

        const int rbase = row0 + mbase + (lane >> 2);
        #pragma unroll
        for (int j = 0; j < 8; ++j) {
            int col = nbase + j * 8 + 2 * (lane & 3);
            float2 bb1 = *reinterpret_cast<const float2*>(smem + SM_B1 + col * 4);
            float2 bb2 = *reinterpret_cast<const float2*>(smem + SM_B2 + col * 4);
            #pragma unroll
            for (int i = 0; i < 2; ++i) {
                int r0 = rbase + i * 16;
                if (r0 < n) {
                    float2 o;
                    o.x = lrelu(c1[i][j][0] + bb1.x) + lrelu(c2[i][j][0] + bb2.x);
                    o.y = lrelu(c1[i][j][1] + bb1.y) + lrelu(c2[i][j][1] + bb2.y);
                    *reinterpret_cast<float2*>(out + (size_t)r0 * D + col) = o;
                }
                int r1 = r0 + 8;
                if (r1 < n) {
                    float2 o;
                    o.x = lrelu(c1[i][j][2] + bb1.x) + lrelu(c2[i][j][2] + bb2.x);
                    o.y = lrelu(c1[i][j][3] + bb1.y) + lrelu(c2[i][j][3] + bb2.y);
                    *reinterpret_cast<float2*>(out + (size_t)r1 * D + col) = o;
                }
            }
        }
        __syncthreads();
        b ^= 1;
    }
}

// ---------------------------------------------------------------------------
// Launch — convert_x forked onto a side stream; CSR chain on main.
// Inputs: x[N*128] f32, src[E] i32, dst[E] i32, e_attn[E] f32,
//         W1[128*128] f32, b1[128] f32, W2[128*128] f32, b2[128] f32
// ---------------------------------------------------------------------------
extern "C" void kernel_launch(void* const* d_in, const int* in_sizes, int n_in,
                              void* d_out, int out_size) {
    const float* x   = (const float*)d_in[0];
    const int*   src = (const int*)  d_in[1];
    const int*   dst = (const int*)  d_in[2];
    const float* ea  = (const float*)d_in[3];
    const float* W1  = (const float*)d_in[4];
    const float* b1  = (const float*)d_in[5];
    const float* W2  = (const float*)d_in[6];
    const float* b2  = (const float*)d_in[7];
    float*       out = (float*)d_out;

    const int n = in_sizes[0] / D;
    const int E = in_sizes[1];

    cudaStream_t s2;
    cudaEvent_t ef, ec;
    cudaStreamCreateWithFlags(&s2, cudaStreamNonBlocking);
    cudaEventCreateWithFlags(&ef, cudaEventDisableTiming);
    cudaEventCreateWithFlags(&ec, cudaEventDisableTiming);

    // fork: convert x -> fp16 on side stream
    cudaEventRecord(ef, 0);
    cudaStreamWaitEvent(s2, ef, 0);
    convert_x_kernel<<<1024, 256, 0, s2>>>(x, n * D / 8);
    cudaEventRecord(ec, s2);

    // CSR chain on main stream (g_cnt pre-zeroed: static init on first call,
    // fill_kernel's end-of-run reset on every replay)
    hist_kernel<<<(E + 255) / 256, 256>>>(dst, E);
    scanoff_kernel<<<256, 256>>>(n);
    fill_kernel<<<(E + 255) / 256, 256>>>(src, dst, ea, E, n);

    // join: gather needs g_xh
    cudaStreamWaitEvent(0, ec, 0);
    gather_kernel<<<(n + 15) / 16, 256>>>(n);

    cudaFuncSetAttribute(gemm_kernel,
                         cudaFuncAttributeMaxDynamicSharedMemorySize, SM_TOT);
    const int ntiles = (n + TILE_M - 1) / TILE_M;
    gemm_kernel<<<148, GT, SM_TOT>>>(W1, b1, W2, b2, out, n, ntiles);

    cudaEventDestroy(ef);
    cudaEventDestroy(ec);
    cudaStreamDestroy(s2);
}